// round 2
// baseline (speedup 1.0000x reference)
#include <cuda_runtime.h>

#define TT 1024
#define BB 32
#define HD 512
#define NG 1536           // 3*HD
#define MM (TT*BB)        // 32768

// ---------------- device scratch (no allocations allowed) ----------------
__device__ float g_gi0[(size_t)MM * NG];     // forward gi  (201 MB)
__device__ float g_gi1[(size_t)MM * NG];     // backward gi (201 MB)
__device__ float g_buf0[(size_t)MM * 1024];  // layer0 output (134 MB)
__device__ float g_buf1[(size_t)MM * 1024];  // layer1 output (134 MB)
__device__ float g_h[2][2][BB * HD];         // ping-pong h per direction
__device__ unsigned g_cnt;                   // grid barrier counter

// ---------------- fp32 NT GEMM with bias:  C[m][n] = sum_k A[m][k]*W[n][k] + bias[n]
// A: M x K row-major, W: N x K row-major, C: M x NG row-major (N = NG = 1536)
// tile 128x128, Ktile 8, 256 threads, 8x8 microtile
__global__ __launch_bounds__(256, 2) void gemm_nt_bias(
    const float* __restrict__ A, const float* __restrict__ W,
    const float* __restrict__ bias, float* __restrict__ C, int K)
{
    __shared__ float As[8][128];
    __shared__ float Ws[8][128];
    int tid = threadIdx.x;
    int tx = tid & 15, ty = tid >> 4;
    int row = tid >> 1;
    int c4  = (tid & 1) * 4;

    const float* Ag = A + (size_t)(blockIdx.x * 128 + row) * K + c4;
    const float* Wg = W + (size_t)(blockIdx.y * 128 + row) * K + c4;

    float acc[8][8];
#pragma unroll
    for (int i = 0; i < 8; i++)
#pragma unroll
        for (int j = 0; j < 8; j++) acc[i][j] = 0.f;

    for (int k0 = 0; k0 < K; k0 += 8) {
        float4 av = *(const float4*)(Ag + k0);
        float4 wv = *(const float4*)(Wg + k0);
        __syncthreads();
        As[c4 + 0][row] = av.x; As[c4 + 1][row] = av.y;
        As[c4 + 2][row] = av.z; As[c4 + 3][row] = av.w;
        Ws[c4 + 0][row] = wv.x; Ws[c4 + 1][row] = wv.y;
        Ws[c4 + 2][row] = wv.z; Ws[c4 + 3][row] = wv.w;
        __syncthreads();
#pragma unroll
        for (int k = 0; k < 8; k++) {
            float ar[8], br[8];
            *(float4*)(ar)     = *(const float4*)&As[k][ty * 4];
            *(float4*)(ar + 4) = *(const float4*)&As[k][64 + ty * 4];
            *(float4*)(br)     = *(const float4*)&Ws[k][tx * 4];
            *(float4*)(br + 4) = *(const float4*)&Ws[k][64 + tx * 4];
#pragma unroll
            for (int i = 0; i < 8; i++)
#pragma unroll
                for (int j = 0; j < 8; j++)
                    acc[i][j] = fmaf(ar[i], br[j], acc[i][j]);
        }
    }

#pragma unroll
    for (int i = 0; i < 8; i++) {
        int m = blockIdx.x * 128 + ((i < 4) ? (ty * 4 + i) : (64 + ty * 4 + (i - 4)));
#pragma unroll
        for (int jj = 0; jj < 2; jj++) {
            int n = blockIdx.y * 128 + ((jj == 0) ? (tx * 4) : (64 + tx * 4));
            float4 bv = *(const float4*)&bias[n];
            float4 o;
            o.x = acc[i][jj * 4 + 0] + bv.x;
            o.y = acc[i][jj * 4 + 1] + bv.y;
            o.z = acc[i][jj * 4 + 2] + bv.z;
            o.w = acc[i][jj * 4 + 3] + bv.w;
            *(float4*)&C[(size_t)m * NG + n] = o;
        }
    }
}

// ---------------- persistent bidirectional GRU scan ----------------
// grid = 128 CTAs x 256 threads. CTA c: dir = c>>6, cid = c&63,
// bhalf = cid&1 (which 16 batches this CTA stages), jblk = cid>>1 (16 j's).
// Warp w handles j0 = jblk*16 + 2w and j0+1; lanes partition k (lane owns k = lane+32i).
__device__ __forceinline__ float sigm(float x) { return 1.f / (1.f + __expf(-x)); }

__global__ __launch_bounds__(256, 1) void gru_scan(
    const float* __restrict__ giF, const float* __restrict__ giB,
    const float* __restrict__ whhF, const float* __restrict__ whhB,
    const float* __restrict__ bhhF, const float* __restrict__ bhhB,
    const float* __restrict__ h0F,  const float* __restrict__ h0B,
    float* __restrict__ out, float* __restrict__ finF, float* __restrict__ finB)
{
    __shared__ float hs[16 * HD];   // 32 KB: this CTA's 16 batches of h

    int c = blockIdx.x;
    int dir = c >> 6;
    int cid = c & 63;
    int bhalf = cid & 1;
    int jblk = cid >> 1;
    int tid = threadIdx.x, w = tid >> 5, lane = tid & 31;
    int j0 = jblk * 16 + w * 2;

    const float* gi  = dir ? giB  : giF;
    const float* whh = dir ? whhB : whhF;
    const float* bhh = dir ? bhhB : bhhF;
    const float* h0  = dir ? h0B  : h0F;
    float* fin = dir ? finB : finF;

    // preload recurrent weights into registers: lane owns k = lane + 32*i
    float wr0[16], wz0[16], wn0[16], wr1[16], wz1[16], wn1[16];
#pragma unroll
    for (int i = 0; i < 16; i++) {
        int k = lane + 32 * i;
        wr0[i] = whh[(0 * HD + j0) * HD + k];
        wz0[i] = whh[(1 * HD + j0) * HD + k];
        wn0[i] = whh[(2 * HD + j0) * HD + k];
        wr1[i] = whh[(0 * HD + j0 + 1) * HD + k];
        wz1[i] = whh[(1 * HD + j0 + 1) * HD + k];
        wn1[i] = whh[(2 * HD + j0 + 1) * HD + k];
    }
    int jl = j0 + (lane >> 4);            // this lane's output j
    int bl = bhalf * 16 + (lane & 15);    // this lane's output b
    float bhr = bhh[jl], bhz = bhh[HD + jl], bhn = bhh[2 * HD + jl];

    unsigned nct = gridDim.x;

    for (int s = 0; s < TT; s++) {
        int t = dir ? (TT - 1 - s) : s;
        // stage h (this CTA's 16 batches) into smem; step s reads buf[s&1]
        const float* hsrc = (s == 0) ? h0 : g_h[dir][s & 1];
        const float4* s4 = (const float4*)(hsrc + bhalf * 16 * HD);
        float4* d4 = (float4*)hs;
#pragma unroll
        for (int i = 0; i < 8; i++) d4[tid + 256 * i] = __ldcg(s4 + tid + 256 * i);

        // prefetch gi for this lane's (t, b, j)
        size_t gb = ((size_t)t * BB + bl) * NG;
        float gir = __ldcg(&gi[gb + jl]);
        float giz = __ldcg(&gi[gb + HD + jl]);
        float gin = __ldcg(&gi[gb + 2 * HD + jl]);
        __syncthreads();

        float mr = 0.f, mz = 0.f, mn = 0.f;
#pragma unroll 2
        for (int b = 0; b < 16; b++) {
            float ar0 = 0.f, az0 = 0.f, an0 = 0.f, ar1 = 0.f, az1 = 0.f, an1 = 0.f;
#pragma unroll
            for (int i = 0; i < 16; i++) {
                float hv = hs[b * HD + lane + 32 * i];
                ar0 = fmaf(hv, wr0[i], ar0); az0 = fmaf(hv, wz0[i], az0); an0 = fmaf(hv, wn0[i], an0);
                ar1 = fmaf(hv, wr1[i], ar1); az1 = fmaf(hv, wz1[i], az1); an1 = fmaf(hv, wn1[i], an1);
            }
#pragma unroll
            for (int o = 16; o > 0; o >>= 1) {
                ar0 += __shfl_xor_sync(0xffffffffu, ar0, o);
                az0 += __shfl_xor_sync(0xffffffffu, az0, o);
                an0 += __shfl_xor_sync(0xffffffffu, an0, o);
                ar1 += __shfl_xor_sync(0xffffffffu, ar1, o);
                az1 += __shfl_xor_sync(0xffffffffu, az1, o);
                an1 += __shfl_xor_sync(0xffffffffu, an1, o);
            }
            if ((lane & 15) == b) {
                mr = (lane < 16) ? ar0 : ar1;
                mz = (lane < 16) ? az0 : az1;
                mn = (lane < 16) ? an0 : an1;
            }
        }

        float r  = sigm(gir + mr + bhr);
        float z  = sigm(giz + mz + bhz);
        float n  = tanhf(gin + r * (mn + bhn));
        float hp = hs[(lane & 15) * HD + jl];
        float hn = (1.f - z) * n + z * hp;

        g_h[dir][(s + 1) & 1][bl * HD + jl] = hn;
        out[((size_t)t * BB + bl) * 1024 + dir * HD + jl] = hn;
        if (s == TT - 1) fin[bl * HD + jl] = hn;

        // grid barrier (monotonic counter; reset kernel zeroes it per layer)
        __syncthreads();
        if (tid == 0) {
            __threadfence();
            atomicAdd(&g_cnt, 1u);
            unsigned target = (unsigned)(s + 1) * nct;
            unsigned v;
            do {
                asm volatile("ld.acquire.gpu.u32 %0, [%1];" : "=r"(v) : "l"(&g_cnt) : "memory");
            } while (v < target);
        }
        __syncthreads();
    }
}

__global__ void reset_cnt() { g_cnt = 0u; }

// ---------------- host launcher ----------------
extern "C" void kernel_launch(void* const* d_in, const int* in_sizes, int n_in,
                              void* d_out, int out_size)
{
    (void)in_sizes; (void)n_in; (void)out_size;
    const float* x  = (const float*)d_in[0];
    const float* h0 = (const float*)d_in[1];
    float* out    = (float*)d_out;
    float* finals = out + (size_t)TT * BB * 1024;

    float *gi0, *gi1, *buf0, *buf1;
    cudaGetSymbolAddress((void**)&gi0,  g_gi0);
    cudaGetSymbolAddress((void**)&gi1,  g_gi1);
    cudaGetSymbolAddress((void**)&buf0, g_buf0);
    cudaGetSymbolAddress((void**)&buf1, g_buf1);

    const float* layin[3]  = { x, buf0, buf1 };
    float*       layout_[3] = { buf0, buf1, out };
    int Ks[3] = { 256, 1024, 1024 };

    dim3 gdim(MM / 128, NG / 128);   // (256, 12)

    for (int L = 0; L < 3; L++) {
        const float* wih  = (const float*)d_in[2 + L * 8 + 0];
        const float* whh  = (const float*)d_in[2 + L * 8 + 1];
        const float* bih  = (const float*)d_in[2 + L * 8 + 2];
        const float* bhh  = (const float*)d_in[2 + L * 8 + 3];
        const float* wihr = (const float*)d_in[2 + L * 8 + 4];
        const float* whhr = (const float*)d_in[2 + L * 8 + 5];
        const float* bihr = (const float*)d_in[2 + L * 8 + 6];
        const float* bhhr = (const float*)d_in[2 + L * 8 + 7];

        gemm_nt_bias<<<gdim, 256>>>(layin[L], wih,  bih,  gi0, Ks[L]);
        gemm_nt_bias<<<gdim, 256>>>(layin[L], wihr, bihr, gi1, Ks[L]);
        reset_cnt<<<1, 1>>>();
        gru_scan<<<128, 256>>>(gi0, gi1, whh, whhr, bhh, bhhr,
                               h0 + (size_t)(2 * L) * BB * HD,
                               h0 + (size_t)(2 * L + 1) * BB * HD,
                               layout_[L],
                               finals + (size_t)(2 * L) * BB * HD,
                               finals + (size_t)(2 * L + 1) * BB * HD);
    }
}

// round 3
// speedup vs baseline: 1.0039x; 1.0039x over previous
#include <cuda_runtime.h>

#define TT 1024
#define BB 32
#define HD 512
#define NG 1536           // 3*HD
#define MM (TT*BB)        // 32768

// ---------------- device scratch (no allocations allowed) ----------------
__device__ float g_gi0[(size_t)MM * NG];     // forward gi  (201 MB)
__device__ float g_gi1[(size_t)MM * NG];     // backward gi (201 MB)
__device__ float g_buf0[(size_t)MM * 1024];  // layer0 output (134 MB)
__device__ float g_buf1[(size_t)MM * 1024];  // layer1 output (134 MB)
__device__ float g_h[2][2][BB * HD];         // ping-pong h per direction
__device__ unsigned g_cnt;                   // grid barrier counter

// ---------------- fp32 NT GEMM with bias:  C[m][n] = sum_k A[m][k]*W[n][k] + bias[n]
// A: M x K row-major, W: N x K row-major, C: M x NG row-major (N = NG = 1536)
// tile 128x128, Ktile 8, 256 threads, 8x8 microtile
__global__ __launch_bounds__(256, 2) void gemm_nt_bias(
    const float* __restrict__ A, const float* __restrict__ W,
    const float* __restrict__ bias, float* __restrict__ C, int K)
{
    __shared__ float As[8][128];
    __shared__ float Ws[8][128];
    int tid = threadIdx.x;
    int tx = tid & 15, ty = tid >> 4;
    int row = tid >> 1;
    int c4  = (tid & 1) * 4;

    const float* Ag = A + (size_t)(blockIdx.x * 128 + row) * K + c4;
    const float* Wg = W + (size_t)(blockIdx.y * 128 + row) * K + c4;

    float acc[8][8];
#pragma unroll
    for (int i = 0; i < 8; i++)
#pragma unroll
        for (int j = 0; j < 8; j++) acc[i][j] = 0.f;

    for (int k0 = 0; k0 < K; k0 += 8) {
        float4 av = *(const float4*)(Ag + k0);
        float4 wv = *(const float4*)(Wg + k0);
        __syncthreads();
        As[c4 + 0][row] = av.x; As[c4 + 1][row] = av.y;
        As[c4 + 2][row] = av.z; As[c4 + 3][row] = av.w;
        Ws[c4 + 0][row] = wv.x; Ws[c4 + 1][row] = wv.y;
        Ws[c4 + 2][row] = wv.z; Ws[c4 + 3][row] = wv.w;
        __syncthreads();
#pragma unroll
        for (int k = 0; k < 8; k++) {
            float ar[8], br[8];
            *(float4*)(ar)     = *(const float4*)&As[k][ty * 4];
            *(float4*)(ar + 4) = *(const float4*)&As[k][64 + ty * 4];
            *(float4*)(br)     = *(const float4*)&Ws[k][tx * 4];
            *(float4*)(br + 4) = *(const float4*)&Ws[k][64 + tx * 4];
#pragma unroll
            for (int i = 0; i < 8; i++)
#pragma unroll
                for (int j = 0; j < 8; j++)
                    acc[i][j] = fmaf(ar[i], br[j], acc[i][j]);
        }
    }

#pragma unroll
    for (int i = 0; i < 8; i++) {
        int m = blockIdx.x * 128 + ((i < 4) ? (ty * 4 + i) : (64 + ty * 4 + (i - 4)));
#pragma unroll
        for (int jj = 0; jj < 2; jj++) {
            int n = blockIdx.y * 128 + ((jj == 0) ? (tx * 4) : (64 + tx * 4));
            float4 bv = *(const float4*)&bias[n];
            float4 o;
            o.x = acc[i][jj * 4 + 0] + bv.x;
            o.y = acc[i][jj * 4 + 1] + bv.y;
            o.z = acc[i][jj * 4 + 2] + bv.z;
            o.w = acc[i][jj * 4 + 3] + bv.w;
            *(float4*)&C[(size_t)m * NG + n] = o;
        }
    }
}

// ---------------- persistent bidirectional GRU scan ----------------
// grid = 128 CTAs x 256 threads. CTA c: dir = c>>6, cid = c&63,
// bhalf = cid&1 (which 16 batches this CTA stages), jblk = cid>>1 (16 j's).
// Warp w handles j0 = jblk*16 + 2w and j0+1; lanes partition k (lane owns k = lane+32i).
__device__ __forceinline__ float sigm(float x) { return 1.f / (1.f + __expf(-x)); }

__global__ __launch_bounds__(256, 1) void gru_scan(
    const float* __restrict__ giF, const float* __restrict__ giB,
    const float* __restrict__ whhF, const float* __restrict__ whhB,
    const float* __restrict__ bhhF, const float* __restrict__ bhhB,
    const float* __restrict__ h0F,  const float* __restrict__ h0B,
    float* __restrict__ out, float* __restrict__ finF, float* __restrict__ finB)
{
    __shared__ float hs[16 * HD];   // 32 KB: this CTA's 16 batches of h

    int c = blockIdx.x;
    int dir = c >> 6;
    int cid = c & 63;
    int bhalf = cid & 1;
    int jblk = cid >> 1;
    int tid = threadIdx.x, w = tid >> 5, lane = tid & 31;
    int j0 = jblk * 16 + w * 2;

    const float* gi  = dir ? giB  : giF;
    const float* whh = dir ? whhB : whhF;
    const float* bhh = dir ? bhhB : bhhF;
    const float* h0  = dir ? h0B  : h0F;
    float* fin = dir ? finB : finF;

    // preload recurrent weights into registers: lane owns k = lane + 32*i
    float wr0[16], wz0[16], wn0[16], wr1[16], wz1[16], wn1[16];
#pragma unroll
    for (int i = 0; i < 16; i++) {
        int k = lane + 32 * i;
        wr0[i] = whh[(0 * HD + j0) * HD + k];
        wz0[i] = whh[(1 * HD + j0) * HD + k];
        wn0[i] = whh[(2 * HD + j0) * HD + k];
        wr1[i] = whh[(0 * HD + j0 + 1) * HD + k];
        wz1[i] = whh[(1 * HD + j0 + 1) * HD + k];
        wn1[i] = whh[(2 * HD + j0 + 1) * HD + k];
    }
    int jl = j0 + (lane >> 4);            // this lane's output j
    int bl = bhalf * 16 + (lane & 15);    // this lane's output b
    float bhr = bhh[jl], bhz = bhh[HD + jl], bhn = bhh[2 * HD + jl];

    unsigned nct = gridDim.x;

    for (int s = 0; s < TT; s++) {
        int t = dir ? (TT - 1 - s) : s;
        // stage h (this CTA's 16 batches) into smem; step s reads buf[s&1]
        const float* hsrc = (s == 0) ? h0 : g_h[dir][s & 1];
        const float4* s4 = (const float4*)(hsrc + bhalf * 16 * HD);
        float4* d4 = (float4*)hs;
#pragma unroll
        for (int i = 0; i < 8; i++) d4[tid + 256 * i] = __ldcg(s4 + tid + 256 * i);

        // prefetch gi for this lane's (t, b, j)
        size_t gb = ((size_t)t * BB + bl) * NG;
        float gir = __ldcg(&gi[gb + jl]);
        float giz = __ldcg(&gi[gb + HD + jl]);
        float gin = __ldcg(&gi[gb + 2 * HD + jl]);
        __syncthreads();

        float mr = 0.f, mz = 0.f, mn = 0.f;
#pragma unroll 2
        for (int b = 0; b < 16; b++) {
            float ar0 = 0.f, az0 = 0.f, an0 = 0.f, ar1 = 0.f, az1 = 0.f, an1 = 0.f;
#pragma unroll
            for (int i = 0; i < 16; i++) {
                float hv = hs[b * HD + lane + 32 * i];
                ar0 = fmaf(hv, wr0[i], ar0); az0 = fmaf(hv, wz0[i], az0); an0 = fmaf(hv, wn0[i], an0);
                ar1 = fmaf(hv, wr1[i], ar1); az1 = fmaf(hv, wz1[i], az1); an1 = fmaf(hv, wn1[i], an1);
            }
#pragma unroll
            for (int o = 16; o > 0; o >>= 1) {
                ar0 += __shfl_xor_sync(0xffffffffu, ar0, o);
                az0 += __shfl_xor_sync(0xffffffffu, az0, o);
                an0 += __shfl_xor_sync(0xffffffffu, an0, o);
                ar1 += __shfl_xor_sync(0xffffffffu, ar1, o);
                az1 += __shfl_xor_sync(0xffffffffu, az1, o);
                an1 += __shfl_xor_sync(0xffffffffu, an1, o);
            }
            if ((lane & 15) == b) {
                mr = (lane < 16) ? ar0 : ar1;
                mz = (lane < 16) ? az0 : az1;
                mn = (lane < 16) ? an0 : an1;
            }
        }

        float r  = sigm(gir + mr + bhr);
        float z  = sigm(giz + mz + bhz);
        float n  = tanhf(gin + r * (mn + bhn));
        float hp = hs[(lane & 15) * HD + jl];
        float hn = (1.f - z) * n + z * hp;

        g_h[dir][(s + 1) & 1][bl * HD + jl] = hn;
        out[((size_t)t * BB + bl) * 1024 + dir * HD + jl] = hn;
        if (s == TT - 1) fin[bl * HD + jl] = hn;

        // grid barrier (monotonic counter; reset kernel zeroes it per layer)
        __syncthreads();
        if (tid == 0) {
            __threadfence();
            atomicAdd(&g_cnt, 1u);
            unsigned target = (unsigned)(s + 1) * nct;
            unsigned v;
            do {
                asm volatile("ld.acquire.gpu.u32 %0, [%1];" : "=r"(v) : "l"(&g_cnt) : "memory");
            } while (v < target);
        }
        __syncthreads();
    }
}

__global__ void reset_cnt() { g_cnt = 0u; }

// ---------------- host launcher ----------------
extern "C" void kernel_launch(void* const* d_in, const int* in_sizes, int n_in,
                              void* d_out, int out_size)
{
    (void)in_sizes; (void)n_in; (void)out_size;
    const float* x  = (const float*)d_in[0];
    const float* h0 = (const float*)d_in[1];
    float* out    = (float*)d_out;
    float* finals = out + (size_t)TT * BB * 1024;

    float *gi0, *gi1, *buf0, *buf1;
    cudaGetSymbolAddress((void**)&gi0,  g_gi0);
    cudaGetSymbolAddress((void**)&gi1,  g_gi1);
    cudaGetSymbolAddress((void**)&buf0, g_buf0);
    cudaGetSymbolAddress((void**)&buf1, g_buf1);

    const float* layin[3]  = { x, buf0, buf1 };
    float*       layout_[3] = { buf0, buf1, out };
    int Ks[3] = { 256, 1024, 1024 };

    dim3 gdim(MM / 128, NG / 128);   // (256, 12)

    for (int L = 0; L < 3; L++) {
        const float* wih  = (const float*)d_in[2 + L * 8 + 0];
        const float* whh  = (const float*)d_in[2 + L * 8 + 1];
        const float* bih  = (const float*)d_in[2 + L * 8 + 2];
        const float* bhh  = (const float*)d_in[2 + L * 8 + 3];
        const float* wihr = (const float*)d_in[2 + L * 8 + 4];
        const float* whhr = (const float*)d_in[2 + L * 8 + 5];
        const float* bihr = (const float*)d_in[2 + L * 8 + 6];
        const float* bhhr = (const float*)d_in[2 + L * 8 + 7];

        gemm_nt_bias<<<gdim, 256>>>(layin[L], wih,  bih,  gi0, Ks[L]);
        gemm_nt_bias<<<gdim, 256>>>(layin[L], wihr, bihr, gi1, Ks[L]);
        reset_cnt<<<1, 1>>>();
        gru_scan<<<128, 256>>>(gi0, gi1, whh, whhr, bhh, bhhr,
                               h0 + (size_t)(2 * L) * BB * HD,
                               h0 + (size_t)(2 * L + 1) * BB * HD,
                               layout_[L],
                               finals + (size_t)(2 * L) * BB * HD,
                               finals + (size_t)(2 * L + 1) * BB * HD);
    }
}

// round 6
// speedup vs baseline: 1.2074x; 1.2027x over previous
#include <cuda_runtime.h>
#include <cstdint>

#define TT 1024
#define BB 32
#define HD 512
#define NG 1536           // 3*HD
#define MM (TT*BB)        // 32768

typedef unsigned long long ull;

// ---------------- device scratch (no allocations allowed) ----------------
__device__ float g_gi0[(size_t)MM * NG];     // forward gi
__device__ float g_gi1[(size_t)MM * NG];     // backward gi
__device__ float g_buf0[(size_t)MM * 1024];  // layer0 output
__device__ float g_buf1[(size_t)MM * 1024];  // layer1 output
__device__ float g_h[2][2][BB * HD];         // ping-pong h per direction
__device__ unsigned g_cnt;                   // grid barrier counter

// ========================= tf32 mma.sync GEMM =========================
// C[m][n] = sum_k A[m][k] * W[n][k] + bias[n]
// A: MxK row-major, W: NxK row-major (= col-major KxN -> row.col mma), C: M x NG.
// Tile 128x128xBK32. 256 threads = 8 warps (4 along M x 2 along N), warp tile 32x64.
#define BM 128
#define BN 128
#define BK 32
#define SSTRIDE 36                      // floats per row in smem (pad: bank = 4g+t, conflict-free)
#define TILE_FLOATS (128 * SSTRIDE)     // 4608 floats = 18 KB
#define GEMM_SMEM (4 * TILE_FLOATS * 4) // 2 buffers x (A+B) = 73728 B

__device__ __forceinline__ unsigned f2tf(float f) {
    unsigned u; asm("cvt.rna.tf32.f32 %0, %1;" : "=r"(u) : "f"(f)); return u;
}
__device__ __forceinline__ void mma8(float* d, const unsigned* a, const unsigned* b) {
    asm volatile("mma.sync.aligned.m16n8k8.row.col.f32.tf32.tf32.f32 "
                 "{%0,%1,%2,%3}, {%4,%5,%6,%7}, {%8,%9}, {%0,%1,%2,%3};"
                 : "+f"(d[0]), "+f"(d[1]), "+f"(d[2]), "+f"(d[3])
                 : "r"(a[0]), "r"(a[1]), "r"(a[2]), "r"(a[3]), "r"(b[0]), "r"(b[1]));
}

__global__ __launch_bounds__(256, 2) void gemm_tc(
    const float* __restrict__ A,
    const float* __restrict__ W0, const float* __restrict__ W1,
    const float* __restrict__ bi0, const float* __restrict__ bi1,
    float* __restrict__ C0, float* __restrict__ C1, int K)
{
    extern __shared__ unsigned smem[];
    unsigned* sA[2] = { smem,                  smem + 2 * TILE_FLOATS };
    unsigned* sB[2] = { smem + TILE_FLOATS,    smem + 3 * TILE_FLOATS };
    __shared__ float sbias[BN];

    int tid = threadIdx.x, warp = tid >> 5, lane = tid & 31;
    int g = lane >> 2, t = lane & 3;
    int wm = (warp & 3) * 32;      // warp M offset (0,32,64,96)
    int wn = (warp >> 2) * 64;     // warp N offset (0,64)

    int n0 = blockIdx.x * BN;
    int m0 = blockIdx.y * BM;
    int dz = blockIdx.z;
    const float* W    = dz ? W1  : W0;
    const float* bias = dz ? bi1 : bi0;
    float*       C    = dz ? C1  : C0;

    if (tid < BN) sbias[tid] = bias[n0 + tid];

    // global load mapping: row = tid>>1 (0..127), 16 floats at col (tid&1)*16
    int grow = tid >> 1, gcol = (tid & 1) * 16;
    const float* Ag = A + (size_t)(m0 + grow) * K + gcol;
    const float* Wg = W + (size_t)(n0 + grow) * K + gcol;

    float acc[2][8][4];
#pragma unroll
    for (int mt = 0; mt < 2; mt++)
#pragma unroll
        for (int nt = 0; nt < 8; nt++)
#pragma unroll
            for (int e = 0; e < 4; e++) acc[mt][nt][e] = 0.f;

    int kT = K / BK;
    float4 av[4], wv[4];

    // preload tile 0
#pragma unroll
    for (int q = 0; q < 4; q++) { av[q] = *(const float4*)(Ag + q * 4); wv[q] = *(const float4*)(Wg + q * 4); }
#pragma unroll
    for (int q = 0; q < 4; q++) {
        unsigned* da = &sA[0][grow * SSTRIDE + gcol + q * 4];
        unsigned* db = &sB[0][grow * SSTRIDE + gcol + q * 4];
        da[0] = f2tf(av[q].x); da[1] = f2tf(av[q].y); da[2] = f2tf(av[q].z); da[3] = f2tf(av[q].w);
        db[0] = f2tf(wv[q].x); db[1] = f2tf(wv[q].y); db[2] = f2tf(wv[q].z); db[3] = f2tf(wv[q].w);
    }
    __syncthreads();

    for (int s = 0; s < kT; s++) {
        int bb = s & 1;
        if (s + 1 < kT) {
            int k0 = (s + 1) * BK;
#pragma unroll
            for (int q = 0; q < 4; q++) {
                av[q] = *(const float4*)(Ag + k0 + q * 4);
                wv[q] = *(const float4*)(Wg + k0 + q * 4);
            }
        }
        // compute on buffer bb
        const unsigned* a_s = sA[bb];
        const unsigned* b_s = sB[bb];
#pragma unroll
        for (int kk = 0; kk < 4; kk++) {
            int k0 = kk * 8;
            unsigned afr[2][4], bfr[8][2];
#pragma unroll
            for (int mt = 0; mt < 2; mt++) {
                int base = (wm + mt * 16 + g) * SSTRIDE + k0 + t;
                afr[mt][0] = a_s[base];
                afr[mt][1] = a_s[base + 8 * SSTRIDE];
                afr[mt][2] = a_s[base + 4];
                afr[mt][3] = a_s[base + 8 * SSTRIDE + 4];
            }
#pragma unroll
            for (int nt = 0; nt < 8; nt++) {
                int base = (wn + nt * 8 + g) * SSTRIDE + k0 + t;
                bfr[nt][0] = b_s[base];
                bfr[nt][1] = b_s[base + 4];
            }
#pragma unroll
            for (int mt = 0; mt < 2; mt++)
#pragma unroll
                for (int nt = 0; nt < 8; nt++)
                    mma8(acc[mt][nt], afr[mt], bfr[nt]);
        }
        if (s + 1 < kT) {
            unsigned* da = &sA[bb ^ 1][grow * SSTRIDE + gcol];
            unsigned* db = &sB[bb ^ 1][grow * SSTRIDE + gcol];
#pragma unroll
            for (int q = 0; q < 4; q++) {
                da[q * 4 + 0] = f2tf(av[q].x); da[q * 4 + 1] = f2tf(av[q].y);
                da[q * 4 + 2] = f2tf(av[q].z); da[q * 4 + 3] = f2tf(av[q].w);
                db[q * 4 + 0] = f2tf(wv[q].x); db[q * 4 + 1] = f2tf(wv[q].y);
                db[q * 4 + 2] = f2tf(wv[q].z); db[q * 4 + 3] = f2tf(wv[q].w);
            }
        }
        __syncthreads();
    }

    // epilogue: d0=(g,2t) d1=(g,2t+1) d2=(g+8,2t) d3=(g+8,2t+1)
#pragma unroll
    for (int mt = 0; mt < 2; mt++) {
        int m = m0 + wm + mt * 16 + g;
#pragma unroll
        for (int nt = 0; nt < 8; nt++) {
            int nl = wn + nt * 8 + 2 * t;
            float b0 = sbias[nl], b1 = sbias[nl + 1];
            float2 v0 = { acc[mt][nt][0] + b0, acc[mt][nt][1] + b1 };
            float2 v1 = { acc[mt][nt][2] + b0, acc[mt][nt][3] + b1 };
            *(float2*)&C[(size_t)m * NG + n0 + nl]       = v0;
            *(float2*)&C[(size_t)(m + 8) * NG + n0 + nl] = v1;
        }
    }
}

// ========================= persistent bidirectional GRU scan =========================
// 128 CTAs x 256 thr. CTA: dir=c>>6, cid=c&63, bhalf=cid&1 (16 batches), jblk=cid>>1 (16 j).
// Warp w: two 16-lane groups g=lane>>4, each group owns j = jblk*16 + w*2 + g.
// Lane l=lane&15 owns k-pairs {2l+32i, 2l+32i+1} -> f32x2 packed MACs, 4-level butterfly.
__device__ __forceinline__ float sigm(float x) { return 1.f / (1.f + __expf(-x)); }
__device__ __forceinline__ ull fma2(ull a, ull b, ull c) {
    ull d; asm("fma.rn.f32x2 %0,%1,%2,%3;" : "=l"(d) : "l"(a), "l"(b), "l"(c)); return d;
}
__device__ __forceinline__ ull add2(ull a, ull b) {
    ull d; asm("add.rn.f32x2 %0,%1,%2;" : "=l"(d) : "l"(a), "l"(b)); return d;
}
__device__ __forceinline__ float red2(ull v) {
    return __uint_as_float((unsigned)v) + __uint_as_float((unsigned)(v >> 32));
}

__global__ __launch_bounds__(256, 1) void gru_scan(
    const float* __restrict__ giF, const float* __restrict__ giB,
    const float* __restrict__ whhF, const float* __restrict__ whhB,
    const float* __restrict__ bhhF, const float* __restrict__ bhhB,
    const float* __restrict__ h0F,  const float* __restrict__ h0B,
    float* __restrict__ out, float* __restrict__ finF, float* __restrict__ finB)
{
    __shared__ float hs[16 * HD];   // 32 KB

    int c = blockIdx.x;
    int dir = c >> 6, cid = c & 63, bhalf = cid & 1, jblk = cid >> 1;
    int tid = threadIdx.x, w = tid >> 5, lane = tid & 31;
    int g = lane >> 4, l = lane & 15;
    int j = jblk * 16 + w * 2 + g;

    const float* gi  = dir ? giB  : giF;
    const float* whh = dir ? whhB : whhF;
    const float* bhh = dir ? bhhB : bhhF;
    const float* h0  = dir ? h0B  : h0F;
    float* fin = dir ? finB : finF;

    ull wr2[16], wz2[16], wn2[16];
#pragma unroll
    for (int i = 0; i < 16; i++) {
        int k = 2 * l + 32 * i;
        wr2[i] = *(const ull*)&whh[(size_t)(0 * HD + j) * HD + k];
        wz2[i] = *(const ull*)&whh[(size_t)(1 * HD + j) * HD + k];
        wn2[i] = *(const ull*)&whh[(size_t)(2 * HD + j) * HD + k];
    }
    int jl = j;
    int bl = bhalf * 16 + l;
    float bhr = bhh[jl], bhz = bhh[HD + jl], bhn = bhh[2 * HD + jl];

    unsigned nct = gridDim.x;

    for (int s = 0; s < TT; s++) {
        int t = dir ? (TT - 1 - s) : s;
        const float* hsrc = (s == 0) ? h0 : g_h[dir][s & 1];
        const float4* s4 = (const float4*)(hsrc + bhalf * 16 * HD);
        float4* d4 = (float4*)hs;
#pragma unroll
        for (int i = 0; i < 8; i++) d4[tid + 256 * i] = __ldcg(s4 + tid + 256 * i);

        size_t gb = ((size_t)t * BB + bl) * NG;
        float gir = __ldcg(&gi[gb + jl]);
        float giz = __ldcg(&gi[gb + HD + jl]);
        float gin = __ldcg(&gi[gb + 2 * HD + jl]);
        __syncthreads();

        float mr = 0.f, mz = 0.f, mn = 0.f;
#pragma unroll 2
        for (int b = 0; b < 16; b++) {
            ull ar = 0, az = 0, an = 0;
            const ull* hp2 = (const ull*)&hs[b * HD + 2 * l];
#pragma unroll
            for (int i = 0; i < 16; i++) {
                ull hv = hp2[i * 16];
                ar = fma2(hv, wr2[i], ar);
                az = fma2(hv, wz2[i], az);
                an = fma2(hv, wn2[i], an);
            }
#pragma unroll
            for (int o = 8; o > 0; o >>= 1) {
                ar = add2(ar, __shfl_xor_sync(0xffffffffu, ar, o));
                az = add2(az, __shfl_xor_sync(0xffffffffu, az, o));
                an = add2(an, __shfl_xor_sync(0xffffffffu, an, o));
            }
            if (l == b) { mr = red2(ar); mz = red2(az); mn = red2(an); }
        }

        float r  = sigm(gir + mr + bhr);
        float z  = sigm(giz + mz + bhz);
        float n  = tanhf(gin + r * (mn + bhn));
        float hp = hs[l * HD + jl];
        float hn = (1.f - z) * n + z * hp;

        g_h[dir][(s + 1) & 1][bl * HD + jl] = hn;
        out[((size_t)t * BB + bl) * 1024 + dir * HD + jl] = hn;
        if (s == TT - 1) fin[bl * HD + jl] = hn;

        __syncthreads();
        if (tid == 0) {
            __threadfence();
            atomicAdd(&g_cnt, 1u);
            unsigned target = (unsigned)(s + 1) * nct;
            unsigned v;
            do {
                asm volatile("ld.acquire.gpu.u32 %0, [%1];" : "=r"(v) : "l"(&g_cnt) : "memory");
            } while (v < target);
        }
        __syncthreads();
    }
}

__global__ void reset_cnt() { g_cnt = 0u; }

// ========================= host launcher =========================
extern "C" void kernel_launch(void* const* d_in, const int* in_sizes, int n_in,
                              void* d_out, int out_size)
{
    (void)in_sizes; (void)n_in; (void)out_size;
    const float* x  = (const float*)d_in[0];
    const float* h0 = (const float*)d_in[1];
    float* out    = (float*)d_out;
    float* finals = out + (size_t)TT * BB * 1024;

    float *gi0, *gi1, *buf0, *buf1;
    cudaGetSymbolAddress((void**)&gi0,  g_gi0);
    cudaGetSymbolAddress((void**)&gi1,  g_gi1);
    cudaGetSymbolAddress((void**)&buf0, g_buf0);
    cudaGetSymbolAddress((void**)&buf1, g_buf1);

    cudaFuncSetAttribute(gemm_tc, cudaFuncAttributeMaxDynamicSharedMemorySize, GEMM_SMEM);

    const float* layin[3]   = { x, buf0, buf1 };
    float*       layout_[3] = { buf0, buf1, out };
    int Ks[3] = { 256, 1024, 1024 };

    dim3 ggrid(NG / BN, MM / BM, 2);   // (12, 256, 2)

    for (int L = 0; L < 3; L++) {
        const float* wih  = (const float*)d_in[2 + L * 8 + 0];
        const float* whh  = (const float*)d_in[2 + L * 8 + 1];
        const float* bih  = (const float*)d_in[2 + L * 8 + 2];
        const float* bhh  = (const float*)d_in[2 + L * 8 + 3];
        const float* wihr = (const float*)d_in[2 + L * 8 + 4];
        const float* whhr = (const float*)d_in[2 + L * 8 + 5];
        const float* bihr = (const float*)d_in[2 + L * 8 + 6];
        const float* bhhr = (const float*)d_in[2 + L * 8 + 7];

        gemm_tc<<<ggrid, 256, GEMM_SMEM>>>(layin[L], wih, wihr, bih, bihr, gi0, gi1, Ks[L]);
        reset_cnt<<<1, 1>>>();
        gru_scan<<<128, 256>>>(gi0, gi1, whh, whhr, bhh, bhhr,
                               h0 + (size_t)(2 * L) * BB * HD,
                               h0 + (size_t)(2 * L + 1) * BB * HD,
                               layout_[L],
                               finals + (size_t)(2 * L) * BB * HD,
                               finals + (size_t)(2 * L + 1) * BB * HD);
    }
}

// round 7
// speedup vs baseline: 1.5051x; 1.2465x over previous
#include <cuda_runtime.h>
#include <cuda_fp16.h>
#include <cstdint>

#define TT 1024
#define BB 32
#define HD 512
#define NG 1536           // 3*HD
#define MM (TT*BB)        // 32768

typedef unsigned long long ull;

// ---------------- device scratch (no allocations allowed) ----------------
__device__ float g_gi0[(size_t)MM * NG];     // forward gi
__device__ float g_gi1[(size_t)MM * NG];     // backward gi
__device__ float g_buf0[(size_t)MM * 1024];  // layer0 output
__device__ float g_buf1[(size_t)MM * 1024];  // layer1 output
__device__ float g_h[2][2][BB * HD];         // ping-pong h per direction
__device__ unsigned g_cnt4[4 * 32];          // 4 independent barrier counters (128B apart)

// ========================= fp16 mma.sync GEMM =========================
// C[m][n] = sum_k A[m][k] * W[n][k] + bias[n]
// A: MxK row-major fp32 -> fp16, W: NxK row-major fp32 -> fp16 (B col-major k x n)
// Tile 128x128xBK32, 256 threads = 8 warps (4 M x 2 N), warp tile 32x64, m16n8k16.
#define BM 128
#define BN 128
#define BK 32
#define SSH 40            // halfs per smem row (32 data + 8 pad; conflict-free)

__device__ __forceinline__ unsigned pack2(float a, float b) {
    __half2 h = __floats2half2_rn(a, b);
    return *(unsigned*)&h;
}
__device__ __forceinline__ void mma16(float* d, const unsigned* a, const unsigned* b) {
    asm volatile("mma.sync.aligned.m16n8k16.row.col.f32.f16.f16.f32 "
                 "{%0,%1,%2,%3}, {%4,%5,%6,%7}, {%8,%9}, {%0,%1,%2,%3};"
                 : "+f"(d[0]), "+f"(d[1]), "+f"(d[2]), "+f"(d[3])
                 : "r"(a[0]), "r"(a[1]), "r"(a[2]), "r"(a[3]), "r"(b[0]), "r"(b[1]));
}

__global__ __launch_bounds__(256, 2) void gemm_tc(
    const float* __restrict__ A,
    const float* __restrict__ W0, const float* __restrict__ W1,
    const float* __restrict__ bi0, const float* __restrict__ bi1,
    float* __restrict__ C0, float* __restrict__ C1, int K)
{
    __shared__ __half sAB[2][2][128 * SSH];   // [buf][A=0/B=1]  40 KB
    __shared__ float sbias[BN];

    int tid = threadIdx.x, warp = tid >> 5, lane = tid & 31;
    int g = lane >> 2, t = lane & 3;
    int wm = (warp & 3) * 32;      // warp M offset
    int wn = (warp >> 2) * 64;     // warp N offset

    int n0 = blockIdx.x * BN;
    int m0 = blockIdx.y * BM;
    int dz = blockIdx.z;
    const float* W    = dz ? W1  : W0;
    const float* bias = dz ? bi1 : bi0;
    float*       C    = dz ? C1  : C0;

    if (tid < BN) sbias[tid] = bias[n0 + tid];

    int grow = tid >> 1, gcol = (tid & 1) * 16;
    const float* Ag = A + (size_t)(m0 + grow) * K + gcol;
    const float* Wg = W + (size_t)(n0 + grow) * K + gcol;

    float acc[2][8][4];
#pragma unroll
    for (int mt = 0; mt < 2; mt++)
#pragma unroll
        for (int nt = 0; nt < 8; nt++)
#pragma unroll
            for (int e = 0; e < 4; e++) acc[mt][nt][e] = 0.f;

    int kT = K / BK;
    float4 av[4], wv[4];

    // preload tile 0
#pragma unroll
    for (int q = 0; q < 4; q++) { av[q] = *(const float4*)(Ag + q * 4); wv[q] = *(const float4*)(Wg + q * 4); }
    {
        uint4 ua0 = { pack2(av[0].x, av[0].y), pack2(av[0].z, av[0].w), pack2(av[1].x, av[1].y), pack2(av[1].z, av[1].w) };
        uint4 ua1 = { pack2(av[2].x, av[2].y), pack2(av[2].z, av[2].w), pack2(av[3].x, av[3].y), pack2(av[3].z, av[3].w) };
        uint4 uw0 = { pack2(wv[0].x, wv[0].y), pack2(wv[0].z, wv[0].w), pack2(wv[1].x, wv[1].y), pack2(wv[1].z, wv[1].w) };
        uint4 uw1 = { pack2(wv[2].x, wv[2].y), pack2(wv[2].z, wv[2].w), pack2(wv[3].x, wv[3].y), pack2(wv[3].z, wv[3].w) };
        *(uint4*)&sAB[0][0][grow * SSH + gcol]     = ua0;
        *(uint4*)&sAB[0][0][grow * SSH + gcol + 8] = ua1;
        *(uint4*)&sAB[0][1][grow * SSH + gcol]     = uw0;
        *(uint4*)&sAB[0][1][grow * SSH + gcol + 8] = uw1;
    }
    __syncthreads();

    for (int s = 0; s < kT; s++) {
        int bb = s & 1;
        if (s + 1 < kT) {
            int k0 = (s + 1) * BK;
#pragma unroll
            for (int q = 0; q < 4; q++) {
                av[q] = *(const float4*)(Ag + k0 + q * 4);
                wv[q] = *(const float4*)(Wg + k0 + q * 4);
            }
        }
        const __half* a_s = sAB[bb][0];
        const __half* b_s = sAB[bb][1];
#pragma unroll
        for (int kk = 0; kk < 2; kk++) {         // 2 x k16 = BK32
            int k0 = kk * 16;
            unsigned afr[2][4], bfr[8][2];
#pragma unroll
            for (int mt = 0; mt < 2; mt++) {
                int base = (wm + mt * 16 + g) * SSH + k0 + 2 * t;
                afr[mt][0] = *(const unsigned*)&a_s[base];
                afr[mt][1] = *(const unsigned*)&a_s[base + 8 * SSH];
                afr[mt][2] = *(const unsigned*)&a_s[base + 8];
                afr[mt][3] = *(const unsigned*)&a_s[base + 8 * SSH + 8];
            }
#pragma unroll
            for (int nt = 0; nt < 8; nt++) {
                int base = (wn + nt * 8 + g) * SSH + k0 + 2 * t;
                bfr[nt][0] = *(const unsigned*)&b_s[base];
                bfr[nt][1] = *(const unsigned*)&b_s[base + 8];
            }
#pragma unroll
            for (int mt = 0; mt < 2; mt++)
#pragma unroll
                for (int nt = 0; nt < 8; nt++)
                    mma16(acc[mt][nt], afr[mt], bfr[nt]);
        }
        if (s + 1 < kT) {
            uint4 ua0 = { pack2(av[0].x, av[0].y), pack2(av[0].z, av[0].w), pack2(av[1].x, av[1].y), pack2(av[1].z, av[1].w) };
            uint4 ua1 = { pack2(av[2].x, av[2].y), pack2(av[2].z, av[2].w), pack2(av[3].x, av[3].y), pack2(av[3].z, av[3].w) };
            uint4 uw0 = { pack2(wv[0].x, wv[0].y), pack2(wv[0].z, wv[0].w), pack2(wv[1].x, wv[1].y), pack2(wv[1].z, wv[1].w) };
            uint4 uw1 = { pack2(wv[2].x, wv[2].y), pack2(wv[2].z, wv[2].w), pack2(wv[3].x, wv[3].y), pack2(wv[3].z, wv[3].w) };
            int nb = bb ^ 1;
            *(uint4*)&sAB[nb][0][grow * SSH + gcol]     = ua0;
            *(uint4*)&sAB[nb][0][grow * SSH + gcol + 8] = ua1;
            *(uint4*)&sAB[nb][1][grow * SSH + gcol]     = uw0;
            *(uint4*)&sAB[nb][1][grow * SSH + gcol + 8] = uw1;
        }
        __syncthreads();
    }

    // epilogue: c0=(g,2t) c1=(g,2t+1) c2=(g+8,2t) c3=(g+8,2t+1)
#pragma unroll
    for (int mt = 0; mt < 2; mt++) {
        int m = m0 + wm + mt * 16 + g;
#pragma unroll
        for (int nt = 0; nt < 8; nt++) {
            int nl = wn + nt * 8 + 2 * t;
            float b0 = sbias[nl], b1 = sbias[nl + 1];
            float2 v0 = { acc[mt][nt][0] + b0, acc[mt][nt][1] + b1 };
            float2 v1 = { acc[mt][nt][2] + b0, acc[mt][nt][3] + b1 };
            *(float2*)&C[(size_t)m * NG + n0 + nl]       = v0;
            *(float2*)&C[(size_t)(m + 8) * NG + n0 + nl] = v1;
        }
    }
}

// ========================= persistent bidirectional GRU scan =========================
// 128 CTAs x 256 thr in 4 INDEPENDENT groups (dir x bhalf), 32 CTAs each, own barrier.
// Warp w: two 16-lane groups g=lane>>4 each own j = jblk*16 + w*2 + g.
// Lane l=lane&15 owns k-pairs {2l+32i} -> f32x2 packed MACs, then f32 4-level butterfly.
__device__ __forceinline__ float sigm(float x) { return 1.f / (1.f + __expf(-x)); }
__device__ __forceinline__ ull fma2(ull a, ull b, ull c) {
    ull d; asm("fma.rn.f32x2 %0,%1,%2,%3;" : "=l"(d) : "l"(a), "l"(b), "l"(c)); return d;
}
__device__ __forceinline__ float red2(ull v) {
    return __uint_as_float((unsigned)v) + __uint_as_float((unsigned)(v >> 32));
}

__global__ __launch_bounds__(256, 1) void gru_scan(
    const float* __restrict__ giF, const float* __restrict__ giB,
    const float* __restrict__ whhF, const float* __restrict__ whhB,
    const float* __restrict__ bhhF, const float* __restrict__ bhhB,
    const float* __restrict__ h0F,  const float* __restrict__ h0B,
    float* __restrict__ out, float* __restrict__ finF, float* __restrict__ finB)
{
    __shared__ float hs[16 * HD];   // 32 KB

    int c = blockIdx.x;
    int dir = c >> 6, cid = c & 63, bhalf = cid & 1, jblk = cid >> 1;
    int grp = dir * 2 + bhalf;
    unsigned* cnt = &g_cnt4[grp * 32];
    int tid = threadIdx.x, w = tid >> 5, lane = tid & 31;
    int g = lane >> 4, l = lane & 15;
    int j = jblk * 16 + w * 2 + g;

    const float* gi  = dir ? giB  : giF;
    const float* whh = dir ? whhB : whhF;
    const float* bhh = dir ? bhhB : bhhF;
    const float* h0  = dir ? h0B  : h0F;
    float* fin = dir ? finB : finF;

    ull wr2[16], wz2[16], wn2[16];
#pragma unroll
    for (int i = 0; i < 16; i++) {
        int k = 2 * l + 32 * i;
        wr2[i] = *(const ull*)&whh[(size_t)(0 * HD + j) * HD + k];
        wz2[i] = *(const ull*)&whh[(size_t)(1 * HD + j) * HD + k];
        wn2[i] = *(const ull*)&whh[(size_t)(2 * HD + j) * HD + k];
    }
    int jl = j;
    int bl = bhalf * 16 + l;
    float bhr = bhh[jl], bhz = bhh[HD + jl], bhn = bhh[2 * HD + jl];

    // prefetch gi for step 0
    float gir, giz, gin;
    {
        int t0 = dir ? (TT - 1) : 0;
        size_t gb = ((size_t)t0 * BB + bl) * NG;
        gir = __ldcg(&gi[gb + jl]);
        giz = __ldcg(&gi[gb + HD + jl]);
        gin = __ldcg(&gi[gb + 2 * HD + jl]);
    }

    for (int s = 0; s < TT; s++) {
        int t = dir ? (TT - 1 - s) : s;
        // stage this group's 16 batches of h into smem
        const float* hsrc = (s == 0) ? h0 : g_h[dir][s & 1];
        const float4* s4 = (const float4*)(hsrc + bhalf * 16 * HD);
        float4* d4 = (float4*)hs;
#pragma unroll
        for (int i = 0; i < 8; i++) d4[tid + 256 * i] = __ldcg(s4 + tid + 256 * i);
        __syncthreads();

        float mr = 0.f, mz = 0.f, mn = 0.f;
#pragma unroll 2
        for (int b = 0; b < 16; b++) {
            ull ar = 0, az = 0, an = 0;
            const ull* hp2 = (const ull*)&hs[b * HD + 2 * l];
#pragma unroll
            for (int i = 0; i < 16; i++) {
                ull hv = hp2[i * 16];
                ar = fma2(hv, wr2[i], ar);
                az = fma2(hv, wz2[i], az);
                an = fma2(hv, wn2[i], an);
            }
            float arf = red2(ar), azf = red2(az), anf = red2(an);
#pragma unroll
            for (int o = 8; o > 0; o >>= 1) {
                arf += __shfl_xor_sync(0xffffffffu, arf, o);
                azf += __shfl_xor_sync(0xffffffffu, azf, o);
                anf += __shfl_xor_sync(0xffffffffu, anf, o);
            }
            if (l == b) { mr = arf; mz = azf; mn = anf; }
        }

        float r  = sigm(gir + mr + bhr);
        float z  = sigm(giz + mz + bhz);
        float n  = tanhf(gin + r * (mn + bhn));
        float hp = hs[l * HD + jl];
        float hn = (1.f - z) * n + z * hp;

        g_h[dir][(s + 1) & 1][bl * HD + jl] = hn;
        out[((size_t)t * BB + bl) * 1024 + dir * HD + jl] = hn;
        if (s == TT - 1) fin[bl * HD + jl] = hn;

        // prefetch gi for step s+1 (issues before the barrier spin -> hidden)
        {
            int s2 = (s + 1 < TT) ? (s + 1) : s;
            int t2 = dir ? (TT - 1 - s2) : s2;
            size_t gb = ((size_t)t2 * BB + bl) * NG;
            gir = __ldcg(&gi[gb + jl]);
            giz = __ldcg(&gi[gb + HD + jl]);
            gin = __ldcg(&gi[gb + 2 * HD + jl]);
        }

        // 32-CTA group barrier (monotonic counter; reset kernel zeroes per layer)
        __syncthreads();
        if (tid == 0) {
            __threadfence();
            atomicAdd(cnt, 1u);
            unsigned target = (unsigned)(s + 1) * 32u;
            unsigned v;
            do {
                asm volatile("ld.acquire.gpu.u32 %0, [%1];" : "=r"(v) : "l"(cnt) : "memory");
            } while (v < target);
        }
        __syncthreads();
    }
}

__global__ void reset_cnt() { if (threadIdx.x < 128) g_cnt4[threadIdx.x] = 0u; }

// ========================= host launcher =========================
extern "C" void kernel_launch(void* const* d_in, const int* in_sizes, int n_in,
                              void* d_out, int out_size)
{
    (void)in_sizes; (void)n_in; (void)out_size;
    const float* x  = (const float*)d_in[0];
    const float* h0 = (const float*)d_in[1];
    float* out    = (float*)d_out;
    float* finals = out + (size_t)TT * BB * 1024;

    float *gi0, *gi1, *buf0, *buf1;
    cudaGetSymbolAddress((void**)&gi0,  g_gi0);
    cudaGetSymbolAddress((void**)&gi1,  g_gi1);
    cudaGetSymbolAddress((void**)&buf0, g_buf0);
    cudaGetSymbolAddress((void**)&buf1, g_buf1);

    const float* layin[3]   = { x, buf0, buf1 };
    float*       layout_[3] = { buf0, buf1, out };
    int Ks[3] = { 256, 1024, 1024 };

    dim3 ggrid(NG / BN, MM / BM, 2);   // (12, 256, 2)

    for (int L = 0; L < 3; L++) {
        const float* wih  = (const float*)d_in[2 + L * 8 + 0];
        const float* whh  = (const float*)d_in[2 + L * 8 + 1];
        const float* bih  = (const float*)d_in[2 + L * 8 + 2];
        const float* bhh  = (const float*)d_in[2 + L * 8 + 3];
        const float* wihr = (const float*)d_in[2 + L * 8 + 4];
        const float* whhr = (const float*)d_in[2 + L * 8 + 5];
        const float* bihr = (const float*)d_in[2 + L * 8 + 6];
        const float* bhhr = (const float*)d_in[2 + L * 8 + 7];

        gemm_tc<<<ggrid, 256>>>(layin[L], wih, wihr, bih, bihr, gi0, gi1, Ks[L]);
        reset_cnt<<<1, 128>>>();
        gru_scan<<<128, 256>>>(gi0, gi1, whh, whhr, bhh, bhhr,
                               h0 + (size_t)(2 * L) * BB * HD,
                               h0 + (size_t)(2 * L + 1) * BB * HD,
                               layout_[L],
                               finals + (size_t)(2 * L) * BB * HD,
                               finals + (size_t)(2 * L + 1) * BB * HD);
    }
}

// round 8
// speedup vs baseline: 2.0061x; 1.3329x over previous
#include <cuda_runtime.h>
#include <cuda_fp16.h>
#include <cstdint>

#define TT 1024
#define BB 32
#define HD 512
#define NG 1536           // 3*HD
#define MM (TT*BB)        // 32768

typedef unsigned long long ull;

// ---------------- device scratch (no allocations allowed) ----------------
__device__ float g_gi0[(size_t)MM * NG];     // forward gi
__device__ float g_gi1[(size_t)MM * NG];     // backward gi
__device__ float g_buf0[(size_t)MM * 1024];  // layer0 output
__device__ float g_buf1[(size_t)MM * 1024];  // layer1 output
__device__ float g_h[2][2][BB * HD];         // ping-pong h per direction
__device__ unsigned g_cnt4[4 * 32];          // 4 independent barrier counters

// ========================= common helpers =========================
__device__ __forceinline__ unsigned pack2(float a, float b) {
    __half2 h = __floats2half2_rn(a, b);
    return *(unsigned*)&h;
}
__device__ __forceinline__ void mma16(float* d, const unsigned* a, const unsigned* b) {
    asm volatile("mma.sync.aligned.m16n8k16.row.col.f32.f16.f16.f32 "
                 "{%0,%1,%2,%3}, {%4,%5,%6,%7}, {%8,%9}, {%0,%1,%2,%3};"
                 : "+f"(d[0]), "+f"(d[1]), "+f"(d[2]), "+f"(d[3])
                 : "r"(a[0]), "r"(a[1]), "r"(a[2]), "r"(a[3]), "r"(b[0]), "r"(b[1]));
}
__device__ __forceinline__ float sigm(float x) { return 1.f / (1.f + __expf(-x)); }

// ========================= fp16 mma.sync projection GEMM =========================
// C[m][n] = sum_k A[m][k]*W[n][k] + bias[n].  Tile 128x128x32, 8 warps (4Mx2N).
#define BM 128
#define BN 128
#define BK 32
#define SSH 40

__global__ __launch_bounds__(256, 2) void gemm_tc(
    const float* __restrict__ A,
    const float* __restrict__ W0, const float* __restrict__ W1,
    const float* __restrict__ bi0, const float* __restrict__ bi1,
    float* __restrict__ C0, float* __restrict__ C1, int K)
{
    __shared__ __half sAB[2][2][128 * SSH];
    __shared__ float sbias[BN];

    int tid = threadIdx.x, warp = tid >> 5, lane = tid & 31;
    int g = lane >> 2, t = lane & 3;
    int wm = (warp & 3) * 32;
    int wn = (warp >> 2) * 64;

    int n0 = blockIdx.x * BN;
    int m0 = blockIdx.y * BM;
    int dz = blockIdx.z;
    const float* W    = dz ? W1  : W0;
    const float* bias = dz ? bi1 : bi0;
    float*       C    = dz ? C1  : C0;

    if (tid < BN) sbias[tid] = bias[n0 + tid];

    int grow = tid >> 1, gcol = (tid & 1) * 16;
    const float* Ag = A + (size_t)(m0 + grow) * K + gcol;
    const float* Wg = W + (size_t)(n0 + grow) * K + gcol;

    float acc[2][8][4];
#pragma unroll
    for (int mt = 0; mt < 2; mt++)
#pragma unroll
        for (int nt = 0; nt < 8; nt++)
#pragma unroll
            for (int e = 0; e < 4; e++) acc[mt][nt][e] = 0.f;

    int kT = K / BK;
    float4 av[4], wv[4];

#pragma unroll
    for (int q = 0; q < 4; q++) { av[q] = *(const float4*)(Ag + q * 4); wv[q] = *(const float4*)(Wg + q * 4); }
    {
        uint4 ua0 = { pack2(av[0].x, av[0].y), pack2(av[0].z, av[0].w), pack2(av[1].x, av[1].y), pack2(av[1].z, av[1].w) };
        uint4 ua1 = { pack2(av[2].x, av[2].y), pack2(av[2].z, av[2].w), pack2(av[3].x, av[3].y), pack2(av[3].z, av[3].w) };
        uint4 uw0 = { pack2(wv[0].x, wv[0].y), pack2(wv[0].z, wv[0].w), pack2(wv[1].x, wv[1].y), pack2(wv[1].z, wv[1].w) };
        uint4 uw1 = { pack2(wv[2].x, wv[2].y), pack2(wv[2].z, wv[2].w), pack2(wv[3].x, wv[3].y), pack2(wv[3].z, wv[3].w) };
        *(uint4*)&sAB[0][0][grow * SSH + gcol]     = ua0;
        *(uint4*)&sAB[0][0][grow * SSH + gcol + 8] = ua1;
        *(uint4*)&sAB[0][1][grow * SSH + gcol]     = uw0;
        *(uint4*)&sAB[0][1][grow * SSH + gcol + 8] = uw1;
    }
    __syncthreads();

    for (int s = 0; s < kT; s++) {
        int bb = s & 1;
        if (s + 1 < kT) {
            int k0 = (s + 1) * BK;
#pragma unroll
            for (int q = 0; q < 4; q++) {
                av[q] = *(const float4*)(Ag + k0 + q * 4);
                wv[q] = *(const float4*)(Wg + k0 + q * 4);
            }
        }
        const __half* a_s = sAB[bb][0];
        const __half* b_s = sAB[bb][1];
#pragma unroll
        for (int kk = 0; kk < 2; kk++) {
            int k0 = kk * 16;
            unsigned afr[2][4], bfr[8][2];
#pragma unroll
            for (int mt = 0; mt < 2; mt++) {
                int base = (wm + mt * 16 + g) * SSH + k0 + 2 * t;
                afr[mt][0] = *(const unsigned*)&a_s[base];
                afr[mt][1] = *(const unsigned*)&a_s[base + 8 * SSH];
                afr[mt][2] = *(const unsigned*)&a_s[base + 8];
                afr[mt][3] = *(const unsigned*)&a_s[base + 8 * SSH + 8];
            }
#pragma unroll
            for (int nt = 0; nt < 8; nt++) {
                int base = (wn + nt * 8 + g) * SSH + k0 + 2 * t;
                bfr[nt][0] = *(const unsigned*)&b_s[base];
                bfr[nt][1] = *(const unsigned*)&b_s[base + 8];
            }
#pragma unroll
            for (int mt = 0; mt < 2; mt++)
#pragma unroll
                for (int nt = 0; nt < 8; nt++)
                    mma16(acc[mt][nt], afr[mt], bfr[nt]);
        }
        if (s + 1 < kT) {
            uint4 ua0 = { pack2(av[0].x, av[0].y), pack2(av[0].z, av[0].w), pack2(av[1].x, av[1].y), pack2(av[1].z, av[1].w) };
            uint4 ua1 = { pack2(av[2].x, av[2].y), pack2(av[2].z, av[2].w), pack2(av[3].x, av[3].y), pack2(av[3].z, av[3].w) };
            uint4 uw0 = { pack2(wv[0].x, wv[0].y), pack2(wv[0].z, wv[0].w), pack2(wv[1].x, wv[1].y), pack2(wv[1].z, wv[1].w) };
            uint4 uw1 = { pack2(wv[2].x, wv[2].y), pack2(wv[2].z, wv[2].w), pack2(wv[3].x, wv[3].y), pack2(wv[3].z, wv[3].w) };
            int nb = bb ^ 1;
            *(uint4*)&sAB[nb][0][grow * SSH + gcol]     = ua0;
            *(uint4*)&sAB[nb][0][grow * SSH + gcol + 8] = ua1;
            *(uint4*)&sAB[nb][1][grow * SSH + gcol]     = uw0;
            *(uint4*)&sAB[nb][1][grow * SSH + gcol + 8] = uw1;
        }
        __syncthreads();
    }

#pragma unroll
    for (int mt = 0; mt < 2; mt++) {
        int m = m0 + wm + mt * 16 + g;
#pragma unroll
        for (int nt = 0; nt < 8; nt++) {
            int nl = wn + nt * 8 + 2 * t;
            float b0 = sbias[nl], b1 = sbias[nl + 1];
            float2 v0 = { acc[mt][nt][0] + b0, acc[mt][nt][1] + b1 };
            float2 v1 = { acc[mt][nt][2] + b0, acc[mt][nt][3] + b1 };
            *(float2*)&C[(size_t)m * NG + n0 + nl]       = v0;
            *(float2*)&C[(size_t)(m + 8) * NG + n0 + nl] = v1;
        }
    }
}

// ========================= tensor-core persistent GRU scan =========================
// 128 CTAs x 256 thr; CTA = (dir, bhalf:16 batches, jblk:16 j). Per step per CTA:
// gh = h(16x512,fp16 via ldmatrix) @ Whh^T(48 cols, fp16 B-frags in REGISTERS), f32 acc.
// Warps 0..5 each own one n8 column tile (48 = 3 gates x 16 j). Gate math on 256 thr.
#define HS 520            // halfs per h16 row (512 + 8 pad)

__global__ __launch_bounds__(256, 1) void gru_scan(
    const float* __restrict__ giF, const float* __restrict__ giB,
    const float* __restrict__ whhF, const float* __restrict__ whhB,
    const float* __restrict__ bhhF, const float* __restrict__ bhhB,
    const float* __restrict__ h0F,  const float* __restrict__ h0B,
    float* __restrict__ out, float* __restrict__ finF, float* __restrict__ finB)
{
    __shared__ __half h16[16 * HS];          // 16.25 KB staged h (fp16)
    __shared__ float sg[3 * 16 * 18];        // gate exchange [gate][b][18]

    int c = blockIdx.x;
    int dir = c >> 6, cid = c & 63, bhalf = cid & 1, jblk = cid >> 1;
    unsigned* cnt = &g_cnt4[(dir * 2 + bhalf) * 32];
    int tid = threadIdx.x, w = tid >> 5, lane = tid & 31;
    int g = lane >> 2, t = lane & 3;

    const float* gi  = dir ? giB  : giF;
    const float* whh = dir ? whhB : whhF;
    const float* bhh = dir ? bhhB : bhhF;
    const float* h0  = dir ? h0B  : h0F;
    float* fin = dir ? finB : finF;

    // ---- epilogue / staging identity: thread (b, jj) ----
    int eb = tid >> 4, ejj = tid & 15;
    int ej  = jblk * 16 + ejj;               // this thread's j
    int ebl = bhalf * 16 + eb;               // this thread's global batch
    float bhr = bhh[ej], bhz = bhh[HD + ej], bhn = bhh[2 * HD + ej];
    float hp = __ldcg(&h0[(size_t)ebl * HD + ej]);   // own h (carried in reg)

    // ---- preload Whh fragments (fp16, registers): warp w<6 owns n8 tile w ----
    unsigned bw[32][2];
    if (w < 6) {
        int nl = w * 8 + g;                  // 0..47
        int gate = nl >> 4, jj = nl & 15;
        const float* Wr = whh + (size_t)(gate * HD + jblk * 16 + jj) * HD;
#pragma unroll
        for (int kk = 0; kk < 32; kk++) {
            int k0 = kk * 16;
            bw[kk][0] = pack2(Wr[k0 + 2 * t],     Wr[k0 + 2 * t + 1]);
            bw[kk][1] = pack2(Wr[k0 + 2 * t + 8], Wr[k0 + 2 * t + 9]);
        }
    }

    uint32_t h16a = (uint32_t)__cvta_generic_to_shared(h16);
    uint32_t lma = h16a + (uint32_t)(((lane & 15) * HS + (lane >> 4) * 8) * 2);
    __half* stg = h16 + eb * HS + ejj * 32;  // staging dest: b=eb, 32 j at ejj*32

    // prefetch gi for step 0
    float gir, giz, gin;
    {
        int t0 = dir ? (TT - 1) : 0;
        size_t gb = ((size_t)t0 * BB + ebl) * NG;
        gir = __ldcg(&gi[gb + ej]);
        giz = __ldcg(&gi[gb + HD + ej]);
        gin = __ldcg(&gi[gb + 2 * HD + ej]);
    }

    for (int s = 0; s < TT; s++) {
        int tt = dir ? (TT - 1 - s) : s;

        // ---- stage h (16 b x 512, fp32 -> fp16 smem) ----
        const float* hsrc = (s == 0) ? h0 : g_h[dir][s & 1];
        {
            const float4* src = (const float4*)(hsrc + (size_t)ebl * HD + ejj * 32);
            float4 v[8];
#pragma unroll
            for (int i = 0; i < 8; i++) v[i] = __ldcg(src + i);
#pragma unroll
            for (int q = 0; q < 4; q++) {
                uint4 u;
                u.x = pack2(v[2 * q].x,     v[2 * q].y);
                u.y = pack2(v[2 * q].z,     v[2 * q].w);
                u.z = pack2(v[2 * q + 1].x, v[2 * q + 1].y);
                u.w = pack2(v[2 * q + 1].z, v[2 * q + 1].w);
                *(uint4*)(stg + q * 8) = u;
            }
        }
        __syncthreads();

        // ---- recurrent GEMM on tensor cores ----
        if (w < 6) {
            float acc[4] = { 0.f, 0.f, 0.f, 0.f };
#pragma unroll
            for (int kk = 0; kk < 32; kk++) {
                unsigned a0, a1, a2, a3;
                asm volatile("ldmatrix.sync.aligned.m8n8.x4.shared.b16 {%0,%1,%2,%3}, [%4];"
                             : "=r"(a0), "=r"(a1), "=r"(a2), "=r"(a3)
                             : "r"(lma + kk * 32));
                unsigned af[4] = { a0, a1, a2, a3 };
                mma16(acc, af, bw[kk]);
            }
            int nl = w * 8 + 2 * t;          // column of c0
            int gate = nl >> 4, jj2 = nl & 15;
            float* p = &sg[gate * 288 + g * 18 + jj2];
            *(float2*)p            = make_float2(acc[0], acc[1]);
            *(float2*)(p + 8 * 18) = make_float2(acc[2], acc[3]);
        }
        __syncthreads();

        // ---- gate math (1 thread = 1 (b,j)) ----
        float gr = sg[0 * 288 + eb * 18 + ejj];
        float gz = sg[1 * 288 + eb * 18 + ejj];
        float gn = sg[2 * 288 + eb * 18 + ejj];
        float r  = sigm(gir + gr + bhr);
        float z  = sigm(giz + gz + bhz);
        float n  = tanhf(gin + r * (gn + bhn));
        float hn = (1.f - z) * n + z * hp;
        hp = hn;

        g_h[dir][(s + 1) & 1][(size_t)ebl * HD + ej] = hn;
        out[((size_t)tt * BB + ebl) * 1024 + dir * HD + ej] = hn;
        if (s == TT - 1) fin[(size_t)ebl * HD + ej] = hn;

        // prefetch next gi (hidden under barrier spin)
        {
            int s2 = (s + 1 < TT) ? (s + 1) : s;
            int t2 = dir ? (TT - 1 - s2) : s2;
            size_t gb = ((size_t)t2 * BB + ebl) * NG;
            gir = __ldcg(&gi[gb + ej]);
            giz = __ldcg(&gi[gb + HD + ej]);
            gin = __ldcg(&gi[gb + 2 * HD + ej]);
        }

        // ---- 32-CTA group barrier ----
        __syncthreads();
        if (tid == 0) {
            __threadfence();
            atomicAdd(cnt, 1u);
            unsigned target = (unsigned)(s + 1) * 32u;
            unsigned v;
            do {
                asm volatile("ld.acquire.gpu.u32 %0, [%1];" : "=r"(v) : "l"(cnt) : "memory");
            } while (v < target);
        }
        __syncthreads();
    }
}

__global__ void reset_cnt() { if (threadIdx.x < 128) g_cnt4[threadIdx.x] = 0u; }

// ========================= host launcher =========================
extern "C" void kernel_launch(void* const* d_in, const int* in_sizes, int n_in,
                              void* d_out, int out_size)
{
    (void)in_sizes; (void)n_in; (void)out_size;
    const float* x  = (const float*)d_in[0];
    const float* h0 = (const float*)d_in[1];
    float* out    = (float*)d_out;
    float* finals = out + (size_t)TT * BB * 1024;

    float *gi0, *gi1, *buf0, *buf1;
    cudaGetSymbolAddress((void**)&gi0,  g_gi0);
    cudaGetSymbolAddress((void**)&gi1,  g_gi1);
    cudaGetSymbolAddress((void**)&buf0, g_buf0);
    cudaGetSymbolAddress((void**)&buf1, g_buf1);

    const float* layin[3]   = { x, buf0, buf1 };
    float*       layout_[3] = { buf0, buf1, out };
    int Ks[3] = { 256, 1024, 1024 };

    dim3 ggrid(NG / BN, MM / BM, 2);   // (12, 256, 2)

    for (int L = 0; L < 3; L++) {
        const float* wih  = (const float*)d_in[2 + L * 8 + 0];
        const float* whh  = (const float*)d_in[2 + L * 8 + 1];
        const float* bih  = (const float*)d_in[2 + L * 8 + 2];
        const float* bhh  = (const float*)d_in[2 + L * 8 + 3];
        const float* wihr = (const float*)d_in[2 + L * 8 + 4];
        const float* whhr = (const float*)d_in[2 + L * 8 + 5];
        const float* bihr = (const float*)d_in[2 + L * 8 + 6];
        const float* bhhr = (const float*)d_in[2 + L * 8 + 7];

        gemm_tc<<<ggrid, 256>>>(layin[L], wih, wihr, bih, bihr, gi0, gi1, Ks[L]);
        reset_cnt<<<1, 128>>>();
        gru_scan<<<128, 256>>>(gi0, gi1, whh, whhr, bhh, bhhr,
                               h0 + (size_t)(2 * L) * BB * HD,
                               h0 + (size_t)(2 * L + 1) * BB * HD,
                               layout_[L],
                               finals + (size_t)(2 * L) * BB * HD,
                               finals + (size_t)(2 * L + 1) * BB * HD);
    }
}